// round 2
// baseline (speedup 1.0000x reference)
#include <cuda_runtime.h>
#include <math.h>

#define Bc 2
#define Lc 1024
#define Dc 1024
#define Hc 16
#define HDc 64
#define FFc 4096
#define NLc 8

// ---------------- scratch (device globals; no allocation) ----------------
__device__ float g_x  [Bc*Lc*Dc];
__device__ float g_tmp[Bc*Lc*Dc];
__device__ float g_q  [Bc*Lc*Dc];
__device__ float g_k  [Bc*Lc*Dc];
__device__ float g_v  [Bc*Lc*Dc];
__device__ float g_o  [Bc*Lc*Dc];
__device__ float g_ff [Bc*Lc*FFc];
__device__ float g_sc [(size_t)Bc*Hc*Lc*Lc];   // 128 MB scores/probs
__device__ float g_pe [Lc*HDc];

__device__ __forceinline__ float gelu_exact(float x) {
    return 0.5f * x * (1.0f + erff(x * 0.70710678118654752f));
}

// ---------------- rope position-embedding table ----------------
// pe[pos][0..31] = cos(pos*invfreq[f]), pe[pos][32..63] = sin(...)
__global__ void pe_k(float* __restrict__ pe) {
    int idx = blockIdx.x * blockDim.x + threadIdx.x;
    if (idx >= Lc * 32) return;
    int pos = idx >> 5, f = idx & 31;
    float inv = powf(10000.0f, -(float)f * (1.0f / 32.0f));
    float ang = (float)pos * inv;
    pe[pos * 64 + f]      = cosf(ang);
    pe[pos * 64 + 32 + f] = sinf(ang);
}

// ---------------- RoPE (in-place on q or k), one warp per (b,l,h) ----------------
__global__ __launch_bounds__(256) void rope_k(float* __restrict__ x, const float* __restrict__ pe) {
    int w    = blockIdx.x * 8 + (threadIdx.x >> 5);
    int lane = threadIdx.x & 31;
    int h = w & 15;
    int l = (w >> 4) & 1023;
    int b = w >> 14;
    float* p = x + ((size_t)(b * Lc + l)) * Dc + h * 64;
    float xe = p[2 * lane];
    float xo = p[2 * lane + 1];
    float c = pe[l * 64 + 2 * lane];
    float s = pe[l * 64 + 2 * lane + 1];
    __syncwarp();
    p[lane]      = xe * c - xo * s;
    p[lane + 32] = xe * s + xo * c;
}

// ---------------- 128x128x8 SGEMM, 8x8 per thread ----------------
// EPI: 0 = +bias ; 1 = +bias then gelu ; 2 = +bias then +res
template<int EPI>
__global__ __launch_bounds__(256) void gemm_k(
    const float* __restrict__ A, const float* __restrict__ Bm,
    const float* __restrict__ bias, const float* __restrict__ res,
    float* __restrict__ C, int M, int N, int K)
{
    __shared__ float As[8][128];
    __shared__ float Bs[8][128];
    const int tid = threadIdx.x;
    const int tx = tid & 15, ty = tid >> 4;
    const int row0 = blockIdx.y * 128, col0 = blockIdx.x * 128;

    const int arow = tid >> 1, acol = (tid & 1) << 2;
    const int brow = tid >> 5, bcol = (tid & 31) << 2;

    float acc[8][8];
#pragma unroll
    for (int i = 0; i < 8; i++)
#pragma unroll
        for (int j = 0; j < 8; j++) acc[i][j] = 0.0f;

    const float* Aptr = A + (size_t)(row0 + arow) * K + acol;
    const float* Bptr = Bm + (size_t)brow * N + col0 + bcol;

    for (int k0 = 0; k0 < K; k0 += 8) {
        float4 av = *(const float4*)(Aptr + k0);
        As[acol + 0][arow] = av.x;
        As[acol + 1][arow] = av.y;
        As[acol + 2][arow] = av.z;
        As[acol + 3][arow] = av.w;
        float4 bv = *(const float4*)(Bptr + (size_t)k0 * N);
        *(float4*)&Bs[brow][bcol] = bv;
        __syncthreads();
#pragma unroll
        for (int kk = 0; kk < 8; kk++) {
            float4 a0 = *(const float4*)&As[kk][ty * 4];
            float4 a1 = *(const float4*)&As[kk][ty * 4 + 64];
            float4 b0 = *(const float4*)&Bs[kk][tx * 4];
            float4 b1 = *(const float4*)&Bs[kk][tx * 4 + 64];
            float a[8] = {a0.x, a0.y, a0.z, a0.w, a1.x, a1.y, a1.z, a1.w};
            float b[8] = {b0.x, b0.y, b0.z, b0.w, b1.x, b1.y, b1.z, b1.w};
#pragma unroll
            for (int i = 0; i < 8; i++)
#pragma unroll
                for (int j = 0; j < 8; j++)
                    acc[i][j] = fmaf(a[i], b[j], acc[i][j]);
        }
        __syncthreads();
    }

#pragma unroll
    for (int ih = 0; ih < 2; ih++)
#pragma unroll
        for (int ii = 0; ii < 4; ii++) {
            int r = row0 + ty * 4 + ih * 64 + ii;
#pragma unroll
            for (int jh = 0; jh < 2; jh++) {
                int c = col0 + tx * 4 + jh * 64;
                float4 bi = *(const float4*)(bias + c);
                float4 vv;
                vv.x = acc[ih * 4 + ii][jh * 4 + 0] + bi.x;
                vv.y = acc[ih * 4 + ii][jh * 4 + 1] + bi.y;
                vv.z = acc[ih * 4 + ii][jh * 4 + 2] + bi.z;
                vv.w = acc[ih * 4 + ii][jh * 4 + 3] + bi.w;
                if (EPI == 1) {
                    vv.x = gelu_exact(vv.x); vv.y = gelu_exact(vv.y);
                    vv.z = gelu_exact(vv.z); vv.w = gelu_exact(vv.w);
                }
                if (EPI == 2) {
                    float4 rr = *(const float4*)(res + (size_t)r * N + c);
                    vv.x += rr.x; vv.y += rr.y; vv.z += rr.z; vv.w += rr.w;
                }
                *(float4*)(C + (size_t)r * N + c) = vv;
            }
        }
}

// ---------------- attention scores: S = Q Kt / 8 + alibi ----------------
// grid (L/64, L/64, B*H)
__global__ __launch_bounds__(256) void scores_k(
    const float* __restrict__ q, const float* __restrict__ k, float* __restrict__ sc)
{
    __shared__ float Qs[64][64];   // [d][m]
    __shared__ float Ks[64][64];   // [d][n]
    int bh = blockIdx.z;
    int b = bh >> 4, h = bh & 15;
    int i0 = blockIdx.y * 64, j0 = blockIdx.x * 64;
    int tid = threadIdx.x;
    int m = tid & 63, dg = tid >> 6;   // dg in 0..3

    const float* qb = q + (size_t)(b * Lc + i0 + m) * Dc + h * 64 + dg * 16;
    const float* kb = k + (size_t)(b * Lc + j0 + m) * Dc + h * 64 + dg * 16;
#pragma unroll
    for (int ii = 0; ii < 4; ii++) {
        int d = dg * 16 + ii * 4;
        float4 vq = *(const float4*)(qb + ii * 4);
        Qs[d + 0][m] = vq.x; Qs[d + 1][m] = vq.y; Qs[d + 2][m] = vq.z; Qs[d + 3][m] = vq.w;
        float4 vk = *(const float4*)(kb + ii * 4);
        Ks[d + 0][m] = vk.x; Ks[d + 1][m] = vk.y; Ks[d + 2][m] = vk.z; Ks[d + 3][m] = vk.w;
    }
    __syncthreads();

    int tx = tid & 15, ty = tid >> 4;
    float acc[4][4];
#pragma unroll
    for (int i = 0; i < 4; i++)
#pragma unroll
        for (int j = 0; j < 4; j++) acc[i][j] = 0.0f;

#pragma unroll 4
    for (int d = 0; d < 64; d++) {
        float4 a  = *(const float4*)&Qs[d][ty * 4];
        float4 bv = *(const float4*)&Ks[d][tx * 4];
        float aa[4] = {a.x, a.y, a.z, a.w};
        float bb[4] = {bv.x, bv.y, bv.z, bv.w};
#pragma unroll
        for (int i = 0; i < 4; i++)
#pragma unroll
            for (int j = 0; j < 4; j++)
                acc[i][j] = fmaf(aa[i], bb[j], acc[i][j]);
    }

    float slope = exp2f(-0.5f * (float)h);
    float* out = sc + (size_t)bh * Lc * Lc;
#pragma unroll
    for (int ii = 0; ii < 4; ii++) {
        int i = i0 + ty * 4 + ii;
#pragma unroll
        for (int jj = 0; jj < 4; jj++) {
            int j = j0 + tx * 4 + jj;
            float bias = (i > j) ? slope * (float)(i - j) : 0.0f;
            out[(size_t)i * Lc + j] = acc[ii][jj] * 0.125f + bias;
        }
    }
}

// ---------------- row softmax over 1024 cols, in place ----------------
__global__ __launch_bounds__(256) void softmax_k(float* __restrict__ sc) {
    size_t row = blockIdx.x;
    float* p = sc + row * Lc;
    int tid = threadIdx.x;
    float4 v = ((float4*)p)[tid];
    __shared__ float red[256];

    float mx = fmaxf(fmaxf(v.x, v.y), fmaxf(v.z, v.w));
    red[tid] = mx; __syncthreads();
    for (int o = 128; o; o >>= 1) { if (tid < o) red[tid] = fmaxf(red[tid], red[tid + o]); __syncthreads(); }
    mx = red[0];
    __syncthreads();

    v.x = expf(v.x - mx); v.y = expf(v.y - mx); v.z = expf(v.z - mx); v.w = expf(v.w - mx);
    red[tid] = v.x + v.y + v.z + v.w; __syncthreads();
    for (int o = 128; o; o >>= 1) { if (tid < o) red[tid] += red[tid + o]; __syncthreads(); }
    float inv = 1.0f / red[0];

    v.x *= inv; v.y *= inv; v.z *= inv; v.w *= inv;
    ((float4*)p)[tid] = v;
}

// ---------------- O = P @ V per (b,h): M=1024, N=64, K=1024 ----------------
// grid (L/64, B*H)
__global__ __launch_bounds__(256) void av_k(
    const float* __restrict__ sc, const float* __restrict__ v, float* __restrict__ o)
{
    __shared__ float Ps[16][64];   // [k][m]
    __shared__ float Vs[16][64];   // [k][d]
    int bh = blockIdx.y;
    int b = bh >> 4, h = bh & 15;
    int l0 = blockIdx.x * 64;
    int tid = threadIdx.x;
    const float* P = sc + (size_t)bh * Lc * Lc;

    int pm = tid & 63, pk = (tid >> 6) * 4;
    int vk = tid >> 4, vd = (tid & 15) * 4;
    int tx = tid & 15, ty = tid >> 4;

    float acc[4][4];
#pragma unroll
    for (int i = 0; i < 4; i++)
#pragma unroll
        for (int j = 0; j < 4; j++) acc[i][j] = 0.0f;

    for (int j0 = 0; j0 < Lc; j0 += 16) {
        float4 pv = *(const float4*)(P + (size_t)(l0 + pm) * Lc + j0 + pk);
        Ps[pk + 0][pm] = pv.x; Ps[pk + 1][pm] = pv.y; Ps[pk + 2][pm] = pv.z; Ps[pk + 3][pm] = pv.w;
        float4 vv = *(const float4*)(v + (size_t)(b * Lc + j0 + vk) * Dc + h * 64 + vd);
        *(float4*)&Vs[vk][vd] = vv;
        __syncthreads();
#pragma unroll
        for (int kk = 0; kk < 16; kk++) {
            float4 a  = *(const float4*)&Ps[kk][ty * 4];
            float4 bv = *(const float4*)&Vs[kk][tx * 4];
            float aa[4] = {a.x, a.y, a.z, a.w};
            float bb[4] = {bv.x, bv.y, bv.z, bv.w};
#pragma unroll
            for (int i = 0; i < 4; i++)
#pragma unroll
                for (int j = 0; j < 4; j++)
                    acc[i][j] = fmaf(aa[i], bb[j], acc[i][j]);
        }
        __syncthreads();
    }

#pragma unroll
    for (int ii = 0; ii < 4; ii++) {
        float4 vv;
        vv.x = acc[ii][0]; vv.y = acc[ii][1]; vv.z = acc[ii][2]; vv.w = acc[ii][3];
        *(float4*)(o + (size_t)(b * Lc + l0 + ty * 4 + ii) * Dc + h * 64 + tx * 4) = vv;
    }
}

// ---------------- LayerNorm over D=1024, one block per row ----------------
__global__ __launch_bounds__(256) void ln_k(
    const float* __restrict__ in, const float* __restrict__ g,
    const float* __restrict__ bt, float* __restrict__ out)
{
    int row = blockIdx.x, tid = threadIdx.x;
    float4 v = ((const float4*)(in + (size_t)row * Dc))[tid];
    __shared__ float red[256];

    red[tid] = v.x + v.y + v.z + v.w; __syncthreads();
    for (int o = 128; o; o >>= 1) { if (tid < o) red[tid] += red[tid + o]; __syncthreads(); }
    float mu = red[0] * (1.0f / Dc);
    __syncthreads();

    float dx = v.x - mu, dy = v.y - mu, dz = v.z - mu, dw = v.w - mu;
    red[tid] = dx * dx + dy * dy + dz * dz + dw * dw; __syncthreads();
    for (int o = 128; o; o >>= 1) { if (tid < o) red[tid] += red[tid + o]; __syncthreads(); }
    float inv = rsqrtf(red[0] * (1.0f / Dc) + 1e-5f);

    float4 gg = ((const float4*)g)[tid];
    float4 bb = ((const float4*)bt)[tid];
    float4 r;
    r.x = dx * inv * gg.x + bb.x;
    r.y = dy * inv * gg.y + bb.y;
    r.z = dz * inv * gg.z + bb.z;
    r.w = dw * inv * gg.w + bb.w;
    ((float4*)(out + (size_t)row * Dc))[tid] = r;
}

// ---------------- host orchestration ----------------
extern "C" void kernel_launch(void* const* d_in, const int* in_sizes, int n_in,
                              void* d_out, int out_size)
{
    const float* src = (const float*)d_in[0];
    const float* Wq  = (const float*)d_in[1];
    const float* bq  = (const float*)d_in[2];
    const float* Wk  = (const float*)d_in[3];
    const float* bk  = (const float*)d_in[4];
    const float* Wv  = (const float*)d_in[5];
    const float* bv  = (const float*)d_in[6];
    const float* Wo  = (const float*)d_in[7];
    const float* bo  = (const float*)d_in[8];
    const float* W1  = (const float*)d_in[9];
    const float* b1  = (const float*)d_in[10];
    const float* W2  = (const float*)d_in[11];
    const float* b2  = (const float*)d_in[12];
    const float* g1  = (const float*)d_in[13];
    const float* be1 = (const float*)d_in[14];
    const float* g2  = (const float*)d_in[15];
    const float* be2 = (const float*)d_in[16];
    const float* gf  = (const float*)d_in[17];
    const float* bf  = (const float*)d_in[18];

    float *x, *tmp, *qb, *kb, *vb, *ob, *ffb, *sc, *pe;
    cudaGetSymbolAddress((void**)&x,   g_x);
    cudaGetSymbolAddress((void**)&tmp, g_tmp);
    cudaGetSymbolAddress((void**)&qb,  g_q);
    cudaGetSymbolAddress((void**)&kb,  g_k);
    cudaGetSymbolAddress((void**)&vb,  g_v);
    cudaGetSymbolAddress((void**)&ob,  g_o);
    cudaGetSymbolAddress((void**)&ffb, g_ff);
    cudaGetSymbolAddress((void**)&sc,  g_sc);
    cudaGetSymbolAddress((void**)&pe,  g_pe);

    cudaMemcpyAsync(x, src, sizeof(float) * Bc * Lc * Dc, cudaMemcpyDeviceToDevice);
    pe_k<<<128, 256>>>(pe);

    const int M = Bc * Lc;                 // 2048
    dim3 gD(Dc / 128, M / 128);            // (8, 16)  N=1024 GEMMs
    dim3 gF(FFc / 128, M / 128);           // (32, 16) N=4096 GEMM
    dim3 gS(Lc / 64, Lc / 64, Bc * Hc);    // scores
    dim3 gAV(Lc / 64, Bc * Hc);            // P@V

    for (int l = 0; l < NLc; l++) {
        const float* wq = Wq + (size_t)l * Dc * Dc;
        const float* wk = Wk + (size_t)l * Dc * Dc;
        const float* wv = Wv + (size_t)l * Dc * Dc;
        const float* wo = Wo + (size_t)l * Dc * Dc;
        const float* w1 = W1 + (size_t)l * Dc * FFc;
        const float* w2 = W2 + (size_t)l * FFc * Dc;

        gemm_k<0><<<gD, 256>>>(x, wq, bq + l * Dc, nullptr, qb, M, Dc, Dc);
        gemm_k<0><<<gD, 256>>>(x, wk, bk + l * Dc, nullptr, kb, M, Dc, Dc);
        gemm_k<0><<<gD, 256>>>(x, wv, bv + l * Dc, nullptr, vb, M, Dc, Dc);

        rope_k<<<(Bc * Lc * Hc) / 8, 256>>>(qb, pe);
        rope_k<<<(Bc * Lc * Hc) / 8, 256>>>(kb, pe);

        scores_k<<<gS, 256>>>(qb, kb, sc);
        softmax_k<<<Bc * Hc * Lc, 256>>>(sc);
        av_k<<<gAV, 256>>>(sc, vb, ob);

        gemm_k<2><<<gD, 256>>>(ob, wo, bo + l * Dc, x, tmp, M, Dc, Dc);
        ln_k<<<M, 256>>>(tmp, g1 + l * Dc, be1 + l * Dc, x);

        gemm_k<1><<<gF, 256>>>(x, w1, b1 + (size_t)l * FFc, nullptr, ffb, M, FFc, Dc);
        gemm_k<2><<<gD, 256>>>(ffb, w2, b2 + l * Dc, x, tmp, M, Dc, FFc);
        ln_k<<<M, 256>>>(tmp, g2 + l * Dc, be2 + l * Dc, x);
    }

    ln_k<<<M, 256>>>(x, gf, bf, (float*)d_out);
}

// round 4
// speedup vs baseline: 2.8865x; 2.8865x over previous
#include <cuda_runtime.h>
#include <cuda_fp16.h>
#include <mma.h>
#include <math.h>
#include <stdint.h>

using namespace nvcuda;

#define Bc 2
#define Lc 1024
#define Dc 1024
#define Hc 16
#define HDc 64
#define FFc 4096
#define NLc 8
#define Mtot (Bc*Lc)

// ---------------- scratch (device globals; no allocation) ----------------
__device__ float g_x  [Mtot*Dc];
__device__ float g_tmp[Mtot*Dc];
__device__ float g_q  [Mtot*Dc];
__device__ float g_k  [Mtot*Dc];
__device__ float g_v  [Mtot*Dc];
__device__ float g_o  [Mtot*Dc];
__device__ float g_raw[(size_t)Mtot*FFc];      // raw GEMM output (fp32), 32 MB
__device__ float g_sc [(size_t)Bc*Hc*Lc*Lc];   // 128 MB scores/probs
__device__ float g_pe [Lc*HDc];

__device__ __half g_xh [Mtot*Dc];
__device__ __half g_oh [Mtot*Dc];
__device__ __half g_ffh[(size_t)Mtot*FFc];
__device__ __half g_wq [(size_t)NLc*Dc*Dc];
__device__ __half g_wk [(size_t)NLc*Dc*Dc];
__device__ __half g_wv [(size_t)NLc*Dc*Dc];
__device__ __half g_wo [(size_t)NLc*Dc*Dc];
__device__ __half g_w1 [(size_t)NLc*Dc*FFc];
__device__ __half g_w2 [(size_t)NLc*FFc*Dc];

__device__ __forceinline__ float gelu_exact(float x) {
    return 0.5f * x * (1.0f + erff(x * 0.70710678118654752f));
}

__device__ __forceinline__ void cp_async16(uint32_t saddr, const void* gaddr) {
    asm volatile("cp.async.cg.shared.global [%0], [%1], 16;" :: "r"(saddr), "l"(gaddr));
}
__device__ __forceinline__ uint32_t smem_u32(const void* p) {
    uint32_t a;
    asm("{ .reg .u64 t; cvta.to.shared.u64 t, %1; cvt.u32.u64 %0, t; }" : "=r"(a) : "l"(p));
    return a;
}

// ================= wmma fp16 GEMM: C[M,N] = A[M,K] @ Bt[N,K]^T (raw fp32 out) =================
// 128x128 tile, BK=32, cp.async double buffer, 8 warps each 64m x 32n.
#define BKc 32
#define LDS 40   // 32 + 8 pad (multiple of 8 for wmma ldm)
__global__ __launch_bounds__(256) void gemm_w(
    const __half* __restrict__ A, const __half* __restrict__ Bt,
    float* __restrict__ C, int M, int N, int K)
{
    __shared__ __half As[2][128][LDS];
    __shared__ __half Bs[2][128][LDS];

    const int tid = threadIdx.x;
    const int w = tid >> 5;
    const int wm = w & 1;          // 0..1 -> 64-row half
    const int wn = w >> 1;         // 0..3 -> 32-col quarter
    const int row0 = blockIdx.y * 128, col0 = blockIdx.x * 128;

    wmma::fragment<wmma::accumulator, 16, 16, 16, float> acc[4][2];
#pragma unroll
    for (int i = 0; i < 4; i++)
#pragma unroll
        for (int j = 0; j < 2; j++) wmma::fill_fragment(acc[i][j], 0.0f);

    // loader: 512 16B-lines per matrix per chunk; 2 per thread per matrix
    const int nch = K / BKc;

    auto issue_chunk = [&](int buf, int c0) {
#pragma unroll
        for (int i = 0; i < 2; i++) {
            int s = tid + i * 256;
            int r = s >> 2, cc = (s & 3) * 8;
            cp_async16(smem_u32(&As[buf][r][cc]), A  + (size_t)(row0 + r) * K + c0 + cc);
            cp_async16(smem_u32(&Bs[buf][r][cc]), Bt + (size_t)(col0 + r) * K + c0 + cc);
        }
        asm volatile("cp.async.commit_group;" ::: "memory");
    };

    issue_chunk(0, 0);

    for (int c = 0; c < nch; c++) {
        const int buf = c & 1;
        if (c + 1 < nch) {
            issue_chunk((c + 1) & 1, (c + 1) * BKc);
            asm volatile("cp.async.wait_group 1;" ::: "memory");
        } else {
            asm volatile("cp.async.wait_group 0;" ::: "memory");
        }
        __syncthreads();

#pragma unroll
        for (int kk = 0; kk < 2; kk++) {
            wmma::fragment<wmma::matrix_a, 16, 16, 16, __half, wmma::row_major> af[4];
            wmma::fragment<wmma::matrix_b, 16, 16, 16, __half, wmma::col_major> bf[2];
#pragma unroll
            for (int i = 0; i < 4; i++)
                wmma::load_matrix_sync(af[i], &As[buf][wm * 64 + i * 16][kk * 16], LDS);
#pragma unroll
            for (int j = 0; j < 2; j++)
                wmma::load_matrix_sync(bf[j], &Bs[buf][wn * 32 + j * 16][kk * 16], LDS);
#pragma unroll
            for (int i = 0; i < 4; i++)
#pragma unroll
                for (int j = 0; j < 2; j++)
                    wmma::mma_sync(acc[i][j], af[i], bf[j], acc[i][j]);
        }
        __syncthreads();
    }

#pragma unroll
    for (int i = 0; i < 4; i++)
#pragma unroll
        for (int j = 0; j < 2; j++)
            wmma::store_matrix_sync(
                C + (size_t)(row0 + wm * 64 + i * 16) * N + col0 + wn * 32 + j * 16,
                acc[i][j], N, wmma::mem_row_major);
}

// ================= epilogue: E0 +bias->f32 ; E1 +bias,gelu->f16 ; E2 +bias,+res->f32 =================
template<int E>
__global__ __launch_bounds__(256) void epi_k(
    const float* __restrict__ raw, const float* __restrict__ bias,
    const float* __restrict__ res, float* __restrict__ outf,
    __half* __restrict__ outh, int N)
{
    size_t i = (size_t)blockIdx.x * 256 + threadIdx.x;   // float4 index
    float4 v = ((const float4*)raw)[i];
    int col = (int)((i * 4) % N);
    float4 b = *(const float4*)(bias + col);
    v.x += b.x; v.y += b.y; v.z += b.z; v.w += b.w;
    if (E == 1) {
        v.x = gelu_exact(v.x); v.y = gelu_exact(v.y);
        v.z = gelu_exact(v.z); v.w = gelu_exact(v.w);
        ((__half2*)outh)[2 * i]     = __floats2half2_rn(v.x, v.y);
        ((__half2*)outh)[2 * i + 1] = __floats2half2_rn(v.z, v.w);
    } else {
        if (E == 2) {
            float4 rr = ((const float4*)res)[i];
            v.x += rr.x; v.y += rr.y; v.z += rr.z; v.w += rr.w;
        }
        ((float4*)outf)[i] = v;
    }
}

// ================= weight transpose + convert: in[K,N] f32 -> out[N,K] f16 =================
__global__ void wconv_t(const float* __restrict__ in, __half* __restrict__ out, int K, int N) {
    __shared__ float t[32][33];
    size_t loff = (size_t)blockIdx.z * K * N;
    int n0 = blockIdx.x * 32, k0 = blockIdx.y * 32;
    int tx = threadIdx.x, ty = threadIdx.y;
#pragma unroll
    for (int i = 0; i < 32; i += 8)
        t[ty + i][tx] = in[loff + (size_t)(k0 + ty + i) * N + n0 + tx];
    __syncthreads();
#pragma unroll
    for (int i = 0; i < 32; i += 8)
        out[loff + (size_t)(n0 + ty + i) * K + k0 + tx] = __float2half_rn(t[tx][ty + i]);
}

// ================= f32 -> f16 elementwise =================
__global__ void f2h_k(const float* __restrict__ in, __half* __restrict__ out, int n4) {
    int i = blockIdx.x * blockDim.x + threadIdx.x;
    if (i >= n4) return;
    float4 v = ((const float4*)in)[i];
    ((__half2*)out)[2 * i]     = __floats2half2_rn(v.x, v.y);
    ((__half2*)out)[2 * i + 1] = __floats2half2_rn(v.z, v.w);
}

// ---------------- rope position-embedding table ----------------
__global__ void pe_k(float* __restrict__ pe) {
    int idx = blockIdx.x * blockDim.x + threadIdx.x;
    if (idx >= Lc * 32) return;
    int pos = idx >> 5, f = idx & 31;
    float inv = powf(10000.0f, -(float)f * (1.0f / 32.0f));
    float ang = (float)pos * inv;
    pe[pos * 64 + f]      = cosf(ang);
    pe[pos * 64 + 32 + f] = sinf(ang);
}

// ---------------- RoPE (in-place), one warp per (b,l,h) ----------------
__global__ __launch_bounds__(256) void rope_k(float* __restrict__ x, const float* __restrict__ pe) {
    int w    = blockIdx.x * 8 + (threadIdx.x >> 5);
    int lane = threadIdx.x & 31;
    int h = w & 15;
    int l = (w >> 4) & 1023;
    int b = w >> 14;
    float* p = x + ((size_t)(b * Lc + l)) * Dc + h * 64;
    float xe = p[2 * lane];
    float xo = p[2 * lane + 1];
    float c = pe[l * 64 + 2 * lane];
    float s = pe[l * 64 + 2 * lane + 1];
    __syncwarp();
    p[lane]      = xe * c - xo * s;
    p[lane + 32] = xe * s + xo * c;
}

// ---------------- attention scores: S = Q Kt / 8 + alibi ----------------
__global__ __launch_bounds__(256) void scores_k(
    const float* __restrict__ q, const float* __restrict__ k, float* __restrict__ sc)
{
    __shared__ float Qs[64][64];
    __shared__ float Ks[64][64];
    int bh = blockIdx.z;
    int b = bh >> 4, h = bh & 15;
    int i0 = blockIdx.y * 64, j0 = blockIdx.x * 64;
    int tid = threadIdx.x;
    int m = tid & 63, dg = tid >> 6;

    const float* qb = q + (size_t)(b * Lc + i0 + m) * Dc + h * 64 + dg * 16;
    const float* kb = k + (size_t)(b * Lc + j0 + m) * Dc + h * 64 + dg * 16;
#pragma unroll
    for (int ii = 0; ii < 4; ii++) {
        int d = dg * 16 + ii * 4;
        float4 vq = *(const float4*)(qb + ii * 4);
        Qs[d + 0][m] = vq.x; Qs[d + 1][m] = vq.y; Qs[d + 2][m] = vq.z; Qs[d + 3][m] = vq.w;
        float4 vk = *(const float4*)(kb + ii * 4);
        Ks[d + 0][m] = vk.x; Ks[d + 1][m] = vk.y; Ks[d + 2][m] = vk.z; Ks[d + 3][m] = vk.w;
    }
    __syncthreads();

    int tx = tid & 15, ty = tid >> 4;
    float acc[4][4];
#pragma unroll
    for (int i = 0; i < 4; i++)
#pragma unroll
        for (int j = 0; j < 4; j++) acc[i][j] = 0.0f;

#pragma unroll 4
    for (int d = 0; d < 64; d++) {
        float4 a  = *(const float4*)&Qs[d][ty * 4];
        float4 bv = *(const float4*)&Ks[d][tx * 4];
        float aa[4] = {a.x, a.y, a.z, a.w};
        float bb[4] = {bv.x, bv.y, bv.z, bv.w};
#pragma unroll
        for (int i = 0; i < 4; i++)
#pragma unroll
            for (int j = 0; j < 4; j++)
                acc[i][j] = fmaf(aa[i], bb[j], acc[i][j]);
    }

    float slope = exp2f(-0.5f * (float)h);
    float* out = sc + (size_t)bh * Lc * Lc;
#pragma unroll
    for (int ii = 0; ii < 4; ii++) {
        int i = i0 + ty * 4 + ii;
#pragma unroll
        for (int jj = 0; jj < 4; jj++) {
            int j = j0 + tx * 4 + jj;
            float bias = (i > j) ? slope * (float)(i - j) : 0.0f;
            out[(size_t)i * Lc + j] = acc[ii][jj] * 0.125f + bias;
        }
    }
}

// ---------------- row softmax over 1024 cols, in place ----------------
__global__ __launch_bounds__(256) void softmax_k(float* __restrict__ sc) {
    size_t row = blockIdx.x;
    float* p = sc + row * Lc;
    int tid = threadIdx.x;
    float4 v = ((float4*)p)[tid];
    __shared__ float red[256];

    float mx = fmaxf(fmaxf(v.x, v.y), fmaxf(v.z, v.w));
    red[tid] = mx; __syncthreads();
    for (int o = 128; o; o >>= 1) { if (tid < o) red[tid] = fmaxf(red[tid], red[tid + o]); __syncthreads(); }
    mx = red[0];
    __syncthreads();

    v.x = expf(v.x - mx); v.y = expf(v.y - mx); v.z = expf(v.z - mx); v.w = expf(v.w - mx);
    red[tid] = v.x + v.y + v.z + v.w; __syncthreads();
    for (int o = 128; o; o >>= 1) { if (tid < o) red[tid] += red[tid + o]; __syncthreads(); }
    float inv = 1.0f / red[0];

    v.x *= inv; v.y *= inv; v.z *= inv; v.w *= inv;
    ((float4*)p)[tid] = v;
}

// ---------------- O = P @ V per (b,h) ----------------
__global__ __launch_bounds__(256) void av_k(
    const float* __restrict__ sc, const float* __restrict__ v, float* __restrict__ o)
{
    __shared__ float Ps[16][64];
    __shared__ float Vs[16][64];
    int bh = blockIdx.y;
    int b = bh >> 4, h = bh & 15;
    int l0 = blockIdx.x * 64;
    int tid = threadIdx.x;
    const float* P = sc + (size_t)bh * Lc * Lc;

    int pm = tid & 63, pk = (tid >> 6) * 4;
    int vk = tid >> 4, vd = (tid & 15) * 4;
    int tx = tid & 15, ty = tid >> 4;

    float acc[4][4];
#pragma unroll
    for (int i = 0; i < 4; i++)
#pragma unroll
        for (int j = 0; j < 4; j++) acc[i][j] = 0.0f;

    for (int j0 = 0; j0 < Lc; j0 += 16) {
        float4 pv = *(const float4*)(P + (size_t)(l0 + pm) * Lc + j0 + pk);
        Ps[pk + 0][pm] = pv.x; Ps[pk + 1][pm] = pv.y; Ps[pk + 2][pm] = pv.z; Ps[pk + 3][pm] = pv.w;
        float4 vv = *(const float4*)(v + (size_t)(b * Lc + j0 + vk) * Dc + h * 64 + vd);
        *(float4*)&Vs[vk][vd] = vv;
        __syncthreads();
#pragma unroll
        for (int kk = 0; kk < 16; kk++) {
            float4 a  = *(const float4*)&Ps[kk][ty * 4];
            float4 bv = *(const float4*)&Vs[kk][tx * 4];
            float aa[4] = {a.x, a.y, a.z, a.w};
            float bb[4] = {bv.x, bv.y, bv.z, bv.w};
#pragma unroll
            for (int i = 0; i < 4; i++)
#pragma unroll
                for (int j = 0; j < 4; j++)
                    acc[i][j] = fmaf(aa[i], bb[j], acc[i][j]);
        }
        __syncthreads();
    }

#pragma unroll
    for (int ii = 0; ii < 4; ii++) {
        float4 vv;
        vv.x = acc[ii][0]; vv.y = acc[ii][1]; vv.z = acc[ii][2]; vv.w = acc[ii][3];
        *(float4*)(o + (size_t)(b * Lc + l0 + ty * 4 + ii) * Dc + h * 64 + tx * 4) = vv;
    }
}

// ---------------- LayerNorm (optionally also writes fp16 copy) ----------------
__global__ __launch_bounds__(256) void ln_k(
    const float* __restrict__ in, const float* __restrict__ g,
    const float* __restrict__ bt, float* __restrict__ out, __half* __restrict__ outh)
{
    int row = blockIdx.x, tid = threadIdx.x;
    float4 v = ((const float4*)(in + (size_t)row * Dc))[tid];
    __shared__ float red[256];

    red[tid] = v.x + v.y + v.z + v.w; __syncthreads();
    for (int o = 128; o; o >>= 1) { if (tid < o) red[tid] += red[tid + o]; __syncthreads(); }
    float mu = red[0] * (1.0f / Dc);
    __syncthreads();

    float dx = v.x - mu, dy = v.y - mu, dz = v.z - mu, dw = v.w - mu;
    red[tid] = dx * dx + dy * dy + dz * dz + dw * dw; __syncthreads();
    for (int o = 128; o; o >>= 1) { if (tid < o) red[tid] += red[tid + o]; __syncthreads(); }
    float inv = rsqrtf(red[0] * (1.0f / Dc) + 1e-5f);

    float4 gg = ((const float4*)g)[tid];
    float4 bb = ((const float4*)bt)[tid];
    float4 r;
    r.x = dx * inv * gg.x + bb.x;
    r.y = dy * inv * gg.y + bb.y;
    r.z = dz * inv * gg.z + bb.z;
    r.w = dw * inv * gg.w + bb.w;
    ((float4*)(out + (size_t)row * Dc))[tid] = r;
    if (outh) {
        ((__half2*)(outh + (size_t)row * Dc))[2 * tid]     = __floats2half2_rn(r.x, r.y);
        ((__half2*)(outh + (size_t)row * Dc))[2 * tid + 1] = __floats2half2_rn(r.z, r.w);
    }
}

// ---------------- host orchestration ----------------
extern "C" void kernel_launch(void* const* d_in, const int* in_sizes, int n_in,
                              void* d_out, int out_size)
{
    const float* src = (const float*)d_in[0];
    const float* Wq  = (const float*)d_in[1];
    const float* bq  = (const float*)d_in[2];
    const float* Wk  = (const float*)d_in[3];
    const float* bk  = (const float*)d_in[4];
    const float* Wv  = (const float*)d_in[5];
    const float* bv  = (const float*)d_in[6];
    const float* Wo  = (const float*)d_in[7];
    const float* bo  = (const float*)d_in[8];
    const float* W1  = (const float*)d_in[9];
    const float* b1  = (const float*)d_in[10];
    const float* W2  = (const float*)d_in[11];
    const float* b2  = (const float*)d_in[12];
    const float* g1  = (const float*)d_in[13];
    const float* be1 = (const float*)d_in[14];
    const float* g2  = (const float*)d_in[15];
    const float* be2 = (const float*)d_in[16];
    const float* gf  = (const float*)d_in[17];
    const float* bf  = (const float*)d_in[18];

    float *x, *tmp, *qb, *kb, *vb, *ob, *raw, *sc, *pe;
    __half *xh, *oh, *ffh, *wqh, *wkh, *wvh, *woh, *w1h, *w2h;
    cudaGetSymbolAddress((void**)&x,   g_x);
    cudaGetSymbolAddress((void**)&tmp, g_tmp);
    cudaGetSymbolAddress((void**)&qb,  g_q);
    cudaGetSymbolAddress((void**)&kb,  g_k);
    cudaGetSymbolAddress((void**)&vb,  g_v);
    cudaGetSymbolAddress((void**)&ob,  g_o);
    cudaGetSymbolAddress((void**)&raw, g_raw);
    cudaGetSymbolAddress((void**)&sc,  g_sc);
    cudaGetSymbolAddress((void**)&pe,  g_pe);
    cudaGetSymbolAddress((void**)&xh,  g_xh);
    cudaGetSymbolAddress((void**)&oh,  g_oh);
    cudaGetSymbolAddress((void**)&ffh, g_ffh);
    cudaGetSymbolAddress((void**)&wqh, g_wq);
    cudaGetSymbolAddress((void**)&wkh, g_wk);
    cudaGetSymbolAddress((void**)&wvh, g_wv);
    cudaGetSymbolAddress((void**)&woh, g_wo);
    cudaGetSymbolAddress((void**)&w1h, g_w1);
    cudaGetSymbolAddress((void**)&w2h, g_w2);

    // weight convert + transpose (fp32 [K,N] -> fp16 [N,K]), all layers at once
    dim3 wblk(32, 8);
    wconv_t<<<dim3(Dc / 32, Dc / 32, NLc), wblk>>>(Wq, wqh, Dc, Dc);
    wconv_t<<<dim3(Dc / 32, Dc / 32, NLc), wblk>>>(Wk, wkh, Dc, Dc);
    wconv_t<<<dim3(Dc / 32, Dc / 32, NLc), wblk>>>(Wv, wvh, Dc, Dc);
    wconv_t<<<dim3(Dc / 32, Dc / 32, NLc), wblk>>>(Wo, woh, Dc, Dc);
    wconv_t<<<dim3(FFc / 32, Dc / 32, NLc), wblk>>>(W1, w1h, Dc, FFc);
    wconv_t<<<dim3(Dc / 32, FFc / 32, NLc), wblk>>>(W2, w2h, FFc, Dc);

    cudaMemcpyAsync(x, src, sizeof(float) * Mtot * Dc, cudaMemcpyDeviceToDevice);
    f2h_k<<<(Mtot * Dc / 4 + 255) / 256, 256>>>(src, xh, Mtot * Dc / 4);
    pe_k<<<128, 256>>>(pe);

    const int M = Mtot;
    dim3 gD(Dc / 128, M / 128);            // (8, 16)
    dim3 gF(FFc / 128, M / 128);           // (32, 16)
    dim3 gS(Lc / 64, Lc / 64, Bc * Hc);
    dim3 gAV(Lc / 64, Bc * Hc);
    const int eD = (M * Dc / 4) / 256;     // epilogue grid, N=1024
    const int eF = (M * FFc / 4) / 256;    // epilogue grid, N=4096

    for (int l = 0; l < NLc; l++) {
        const __half* wq = wqh + (size_t)l * Dc * Dc;
        const __half* wk = wkh + (size_t)l * Dc * Dc;
        const __half* wv = wvh + (size_t)l * Dc * Dc;
        const __half* wo = woh + (size_t)l * Dc * Dc;
        const __half* w1 = w1h + (size_t)l * Dc * FFc;
        const __half* w2 = w2h + (size_t)l * FFc * Dc;

        gemm_w<<<gD, 256>>>(xh, wq, raw, M, Dc, Dc);
        epi_k<0><<<eD, 256>>>(raw, bq + l * Dc, nullptr, qb, nullptr, Dc);
        gemm_w<<<gD, 256>>>(xh, wk, raw, M, Dc, Dc);
        epi_k<0><<<eD, 256>>>(raw, bk + l * Dc, nullptr, kb, nullptr, Dc);
        gemm_w<<<gD, 256>>>(xh, wv, raw, M, Dc, Dc);
        epi_k<0><<<eD, 256>>>(raw, bv + l * Dc, nullptr, vb, nullptr, Dc);

        rope_k<<<(Mtot * Hc) / 8, 256>>>(qb, pe);
        rope_k<<<(Mtot * Hc) / 8, 256>>>(kb, pe);

        scores_k<<<gS, 256>>>(qb, kb, sc);
        softmax_k<<<Bc * Hc * Lc, 256>>>(sc);
        av_k<<<gAV, 256>>>(sc, vb, ob);

        f2h_k<<<(Mtot * Dc / 4 + 255) / 256, 256>>>(ob, oh, Mtot * Dc / 4);
        gemm_w<<<gD, 256>>>(oh, wo, raw, M, Dc, Dc);
        epi_k<2><<<eD, 256>>>(raw, bo + l * Dc, x, tmp, nullptr, Dc);
        ln_k<<<M, 256>>>(tmp, g1 + l * Dc, be1 + l * Dc, x, xh);

        gemm_w<<<gF, 256>>>(xh, w1, raw, M, FFc, Dc);
        epi_k<1><<<eF, 256>>>(raw, b1 + (size_t)l * FFc, nullptr, nullptr, ffh, FFc);
        gemm_w<<<gD, 256>>>(ffh, w2, raw, M, Dc, FFc);
        epi_k<2><<<eD, 256>>>(raw, b2 + l * Dc, x, tmp, nullptr, Dc);
        ln_k<<<M, 256>>>(tmp, g2 + l * Dc, be2 + l * Dc, x, xh);
    }

    ln_k<<<M, 256>>>(x, gf, bf, (float*)d_out, nullptr);
}

// round 5
// speedup vs baseline: 3.0426x; 1.0541x over previous
#include <cuda_runtime.h>
#include <cuda_fp16.h>
#include <mma.h>
#include <math.h>
#include <stdint.h>

using namespace nvcuda;

#define Bc 2
#define Lc 1024
#define Dc 1024
#define Hc 16
#define HDc 64
#define FFc 4096
#define NLc 8
#define Mtot (Bc*Lc)

// ---------------- scratch (device globals; no allocation) ----------------
__device__ float g_x  [Mtot*Dc];
__device__ float g_tmp[Mtot*Dc];
__device__ float g_q  [Mtot*Dc];
__device__ float g_k  [Mtot*Dc];
__device__ float g_pe [Lc*HDc];

__device__ __half g_xh [Mtot*Dc];
__device__ __half g_qh [Mtot*Dc];
__device__ __half g_kh [Mtot*Dc];
__device__ __half g_vh [Mtot*Dc];
__device__ __half g_oh [Mtot*Dc];
__device__ __half g_ffh[(size_t)Mtot*FFc];
__device__ __half g_wq [(size_t)NLc*Dc*Dc];
__device__ __half g_wk [(size_t)NLc*Dc*Dc];
__device__ __half g_wv [(size_t)NLc*Dc*Dc];
__device__ __half g_wo [(size_t)NLc*Dc*Dc];
__device__ __half g_w1 [(size_t)NLc*Dc*FFc];
__device__ __half g_w2 [(size_t)NLc*FFc*Dc];

__device__ __forceinline__ float gelu_exact(float x) {
    return 0.5f * x * (1.0f + erff(x * 0.70710678118654752f));
}
__device__ __forceinline__ void cp_async16(uint32_t saddr, const void* gaddr) {
    asm volatile("cp.async.cg.shared.global [%0], [%1], 16;" :: "r"(saddr), "l"(gaddr));
}
__device__ __forceinline__ uint32_t smem_u32(const void* p) {
    uint32_t a;
    asm("{ .reg .u64 t; cvta.to.shared.u64 t, %1; cvt.u32.u64 %0, t; }" : "=r"(a) : "l"(p));
    return a;
}

// ================= wmma fp16 GEMM with fused epilogue =================
// C[M,N] = A[M,K] @ Bt[N,K]^T ; E0: f32 +bias ; E1: f16 +bias ; E2: f16 gelu(+bias) ; E3: f32 +bias+res
#define BKc 32
#define LDS 40
#define GEMM_DSM (128*132*4)   // 67584 B (C tile), > 40960 B (A/B double buffers) -> union
template<int E>
__global__ __launch_bounds__(256) void gemm_w(
    const __half* __restrict__ A, const __half* __restrict__ Bt,
    const float* __restrict__ bias, const float* __restrict__ res,
    float* __restrict__ Cf, __half* __restrict__ Ch, int M, int N, int K)
{
    extern __shared__ char dsm[];
    __half (*As)[128][LDS] = (__half (*)[128][LDS])dsm;
    __half (*Bs)[128][LDS] = (__half (*)[128][LDS])(dsm + 2 * 128 * LDS * 2);
    float* Cs = (float*)dsm;   // aliased; used after mainloop

    const int tid = threadIdx.x;
    const int w = tid >> 5;
    const int wm = w & 1;
    const int wn = w >> 1;
    const int row0 = blockIdx.y * 128, col0 = blockIdx.x * 128;

    wmma::fragment<wmma::accumulator, 16, 16, 16, float> acc[4][2];
#pragma unroll
    for (int i = 0; i < 4; i++)
#pragma unroll
        for (int j = 0; j < 2; j++) wmma::fill_fragment(acc[i][j], 0.0f);

    const int nch = K / BKc;
    auto issue_chunk = [&](int buf, int c0) {
#pragma unroll
        for (int i = 0; i < 2; i++) {
            int s = tid + i * 256;
            int r = s >> 2, cc = (s & 3) * 8;
            cp_async16(smem_u32(&As[buf][r][cc]), A  + (size_t)(row0 + r) * K + c0 + cc);
            cp_async16(smem_u32(&Bs[buf][r][cc]), Bt + (size_t)(col0 + r) * K + c0 + cc);
        }
        asm volatile("cp.async.commit_group;" ::: "memory");
    };

    issue_chunk(0, 0);
    for (int c = 0; c < nch; c++) {
        const int buf = c & 1;
        if (c + 1 < nch) {
            issue_chunk((c + 1) & 1, (c + 1) * BKc);
            asm volatile("cp.async.wait_group 1;" ::: "memory");
        } else {
            asm volatile("cp.async.wait_group 0;" ::: "memory");
        }
        __syncthreads();
#pragma unroll
        for (int kk = 0; kk < 2; kk++) {
            wmma::fragment<wmma::matrix_a, 16, 16, 16, __half, wmma::row_major> af[4];
            wmma::fragment<wmma::matrix_b, 16, 16, 16, __half, wmma::col_major> bf[2];
#pragma unroll
            for (int i = 0; i < 4; i++)
                wmma::load_matrix_sync(af[i], &As[buf][wm * 64 + i * 16][kk * 16], LDS);
#pragma unroll
            for (int j = 0; j < 2; j++)
                wmma::load_matrix_sync(bf[j], &Bs[buf][wn * 32 + j * 16][kk * 16], LDS);
#pragma unroll
            for (int i = 0; i < 4; i++)
#pragma unroll
                for (int j = 0; j < 2; j++)
                    wmma::mma_sync(acc[i][j], af[i], bf[j], acc[i][j]);
        }
        __syncthreads();
    }

    // stage C tile through smem (aliased with A/B buffers; all MMA done)
#pragma unroll
    for (int i = 0; i < 4; i++)
#pragma unroll
        for (int j = 0; j < 2; j++)
            wmma::store_matrix_sync(Cs + (size_t)(wm * 64 + i * 16) * 132 + wn * 32 + j * 16,
                                    acc[i][j], 132, wmma::mem_row_major);
    __syncthreads();

#pragma unroll
    for (int it = 0; it < 16; it++) {
        int vlin = tid + it * 256;
        int row = vlin >> 5;
        int vc = (vlin & 31) * 4;
        float4 v = *(float4*)(Cs + (size_t)row * 132 + vc);
        float4 b = *(const float4*)(bias + col0 + vc);
        v.x += b.x; v.y += b.y; v.z += b.z; v.w += b.w;
        size_t gidx = (size_t)(row0 + row) * N + col0 + vc;
        if (E == 2) {
            v.x = gelu_exact(v.x); v.y = gelu_exact(v.y);
            v.z = gelu_exact(v.z); v.w = gelu_exact(v.w);
        }
        if (E == 1 || E == 2) {
            *(__half2*)(Ch + gidx)     = __floats2half2_rn(v.x, v.y);
            *(__half2*)(Ch + gidx + 2) = __floats2half2_rn(v.z, v.w);
        } else {
            if (E == 3) {
                float4 rr = *(const float4*)(res + gidx);
                v.x += rr.x; v.y += rr.y; v.z += rr.z; v.w += rr.w;
            }
            *(float4*)(Cf + gidx) = v;
        }
    }
}

// ================= fused flash attention =================
// grid (L/128, B*H); block 256 (8 warps). q is pre-scaled by 1/8 and fp16; k,v fp16.
// S/Otmp alias. Online softmax in fp32. Output fp16 o.
#define FA_Q   0
#define FA_K   16384
#define FA_V   24576
#define FA_S   32768              // 128x64 f32, aliased with Otmp
#define FA_P   65536              // 128x64 f16
#define FA_O   81920              // 128x64 f32
#define FA_M   114688
#define FA_L   (114688 + 512)
#define FA_F   (114688 + 1024)
#define FA_DSM (114688 + 1536)
__global__ __launch_bounds__(256) void fa_k(
    const __half* __restrict__ q, const __half* __restrict__ k,
    const __half* __restrict__ v, __half* __restrict__ o)
{
    extern __shared__ char dsm[];
    __half* Qs = (__half*)(dsm + FA_Q);
    __half* Ks = (__half*)(dsm + FA_K);
    __half* Vs = (__half*)(dsm + FA_V);
    float*  Ss = (float*)(dsm + FA_S);
    __half* Ps = (__half*)(dsm + FA_P);
    float*  Os = (float*)(dsm + FA_O);
    float*  mrow = (float*)(dsm + FA_M);
    float*  lrow = (float*)(dsm + FA_L);
    float*  frow = (float*)(dsm + FA_F);

    const int tid = threadIdx.x;
    const int w = tid >> 5;
    const int bh = blockIdx.y;
    const int b = bh >> 4, h = bh & 15;
    const int i0 = blockIdx.x * 128;
    const float slope = exp2f(-0.5f * (float)h);

    // load Q tile (128 x 64 f16)
#pragma unroll
    for (int i = 0; i < 4; i++) {
        int s = tid + i * 256;
        int r = s >> 3, u = (s & 7) * 8;
        *(uint4*)(Qs + r * 64 + u) = *(const uint4*)(q + (size_t)(b * Lc + i0 + r) * Dc + h * 64 + u);
    }
    // init O, m, l
#pragma unroll
    for (int i = 0; i < 8; i++)
        *(float4*)(Os + tid * 4 + i * 1024) = make_float4(0.f, 0.f, 0.f, 0.f);
    if (tid < 128) { mrow[tid] = -1e30f; lrow[tid] = 0.0f; }
    __syncthreads();

    const int row = tid >> 1;
    const int cbase = (tid & 1) * 32;
    const int i_abs = i0 + row;

    for (int jt = 0; jt < Lc / 64; jt++) {
        const int j0 = jt * 64;
        // load K,V tiles (64 x 64 f16 each)
#pragma unroll
        for (int i = 0; i < 2; i++) {
            int s = tid + i * 256;
            int r = s >> 3, u = (s & 7) * 8;
            *(uint4*)(Ks + r * 64 + u) = *(const uint4*)(k + (size_t)(b * Lc + j0 + r) * Dc + h * 64 + u);
            *(uint4*)(Vs + r * 64 + u) = *(const uint4*)(v + (size_t)(b * Lc + j0 + r) * Dc + h * 64 + u);
        }
        __syncthreads();

        // S = Q @ K^T : warp w computes rows w*16..+15, all 64 cols
        {
            wmma::fragment<wmma::matrix_a, 16, 16, 16, __half, wmma::row_major> af[4];
#pragma unroll
            for (int kk = 0; kk < 4; kk++)
                wmma::load_matrix_sync(af[kk], Qs + (w * 16) * 64 + kk * 16, 64);
#pragma unroll
            for (int n = 0; n < 4; n++) {
                wmma::fragment<wmma::accumulator, 16, 16, 16, float> c;
                wmma::fill_fragment(c, 0.0f);
#pragma unroll
                for (int kk = 0; kk < 4; kk++) {
                    wmma::fragment<wmma::matrix_b, 16, 16, 16, __half, wmma::col_major> bf;
                    wmma::load_matrix_sync(bf, Ks + (n * 16) * 64 + kk * 16, 64);
                    wmma::mma_sync(c, af[kk], bf, c);
                }
                wmma::store_matrix_sync(Ss + (w * 16) * 64 + n * 16, c, 64, wmma::mem_row_major);
            }
        }
        __syncthreads();

        // online softmax: thread handles (row, cols cbase..cbase+31)
        {
            float s[32];
            float mx = -1e30f;
#pragma unroll
            for (int c = 0; c < 32; c++) {
                int j_abs = j0 + cbase + c;
                float bias = (i_abs > j_abs) ? slope * (float)(i_abs - j_abs) : 0.0f;
                s[c] = Ss[row * 64 + cbase + c] + bias;
                mx = fmaxf(mx, s[c]);
            }
            float mx2 = fmaxf(mx, __shfl_xor_sync(0xffffffffu, mx, 1));
            float m_old = mrow[row];
            float m_new = fmaxf(m_old, mx2);
            float factor = __expf(m_old - m_new);
            float sum = 0.0f;
#pragma unroll
            for (int c = 0; c < 32; c += 2) {
                float p0 = __expf(s[c] - m_new);
                float p1 = __expf(s[c + 1] - m_new);
                sum += p0 + p1;
                *(__half2*)(Ps + row * 64 + cbase + c) = __floats2half2_rn(p0, p1);
            }
            float sum2 = sum + __shfl_xor_sync(0xffffffffu, sum, 1);
            if ((tid & 1) == 0) {
                mrow[row] = m_new;
                lrow[row] = lrow[row] * factor + sum2;
                frow[row] = factor;
            }
        }
        __syncthreads();

        // Onew = P @ V -> Ss (reused as Otmp)
        {
            wmma::fragment<wmma::matrix_a, 16, 16, 16, __half, wmma::row_major> af[4];
#pragma unroll
            for (int kk = 0; kk < 4; kk++)
                wmma::load_matrix_sync(af[kk], Ps + (w * 16) * 64 + kk * 16, 64);
#pragma unroll
            for (int n = 0; n < 4; n++) {
                wmma::fragment<wmma::accumulator, 16, 16, 16, float> c;
                wmma::fill_fragment(c, 0.0f);
#pragma unroll
                for (int kk = 0; kk < 4; kk++) {
                    wmma::fragment<wmma::matrix_b, 16, 16, 16, __half, wmma::row_major> bf;
                    wmma::load_matrix_sync(bf, Vs + (kk * 16) * 64 + n * 16, 64);
                    wmma::mma_sync(c, af[kk], bf, c);
                }
                wmma::store_matrix_sync(Ss + (w * 16) * 64 + n * 16, c, 64, wmma::mem_row_major);
            }
        }
        __syncthreads();

        // O = O*factor + Onew
        {
            float f = frow[row];
#pragma unroll
            for (int qd = 0; qd < 8; qd++) {
                int idx = row * 64 + cbase + qd * 4;
                float4 ov = *(float4*)(Os + idx);
                float4 nv = *(float4*)(Ss + idx);
                ov.x = ov.x * f + nv.x; ov.y = ov.y * f + nv.y;
                ov.z = ov.z * f + nv.z; ov.w = ov.w * f + nv.w;
                *(float4*)(Os + idx) = ov;
            }
        }
        __syncthreads();
    }

    // final: o = O / l  (fp16 out)
    {
        float inv = 1.0f / lrow[row];
        size_t gb = (size_t)(b * Lc + i_abs) * Dc + h * 64 + cbase;
#pragma unroll
        for (int c = 0; c < 32; c += 2) {
            float2 p;
            p.x = Os[row * 64 + cbase + c] * inv;
            p.y = Os[row * 64 + cbase + c + 1] * inv;
            *(__half2*)(o + gb + c) = __floats2half2_rn(p.x, p.y);
        }
    }
}

// ================= weight transpose + convert: in[K,N] f32 -> out[N,K] f16 =================
__global__ void wconv_t(const float* __restrict__ in, __half* __restrict__ out, int K, int N) {
    __shared__ float t[32][33];
    size_t loff = (size_t)blockIdx.z * K * N;
    int n0 = blockIdx.x * 32, k0 = blockIdx.y * 32;
    int tx = threadIdx.x, ty = threadIdx.y;
#pragma unroll
    for (int i = 0; i < 32; i += 8)
        t[ty + i][tx] = in[loff + (size_t)(k0 + ty + i) * N + n0 + tx];
    __syncthreads();
#pragma unroll
    for (int i = 0; i < 32; i += 8)
        out[loff + (size_t)(n0 + ty + i) * K + k0 + tx] = __float2half_rn(t[tx][ty + i]);
}

// ================= f32 -> f16 elementwise =================
__global__ void f2h_k(const float* __restrict__ in, __half* __restrict__ out, int n4) {
    int i = blockIdx.x * blockDim.x + threadIdx.x;
    if (i >= n4) return;
    float4 v = ((const float4*)in)[i];
    ((__half2*)out)[2 * i]     = __floats2half2_rn(v.x, v.y);
    ((__half2*)out)[2 * i + 1] = __floats2half2_rn(v.z, v.w);
}

// ---------------- rope position-embedding table ----------------
__global__ void pe_k(float* __restrict__ pe) {
    int idx = blockIdx.x * blockDim.x + threadIdx.x;
    if (idx >= Lc * 32) return;
    int pos = idx >> 5, f = idx & 31;
    float inv = powf(10000.0f, -(float)f * (1.0f / 32.0f));
    float ang = (float)pos * inv;
    pe[pos * 64 + f]      = cosf(ang);
    pe[pos * 64 + 32 + f] = sinf(ang);
}

// ---------------- RoPE: fp32 in -> fp16 out (optionally scaled), one warp per (b,l,h) ----------------
__global__ __launch_bounds__(256) void rope_h(
    const float* __restrict__ x, const float* __restrict__ pe,
    __half* __restrict__ out, float scale)
{
    int w    = blockIdx.x * 8 + (threadIdx.x >> 5);
    int lane = threadIdx.x & 31;
    int h = w & 15;
    int l = (w >> 4) & 1023;
    int b = w >> 14;
    const float* p = x + ((size_t)(b * Lc + l)) * Dc + h * 64;
    __half* po = out + ((size_t)(b * Lc + l)) * Dc + h * 64;
    float xe = p[2 * lane];
    float xo = p[2 * lane + 1];
    float c = pe[l * 64 + 2 * lane];
    float s = pe[l * 64 + 2 * lane + 1];
    po[lane]      = __float2half_rn((xe * c - xo * s) * scale);
    po[lane + 32] = __float2half_rn((xe * s + xo * c) * scale);
}

// ---------------- LayerNorm (writes fp32 + optional fp16 copy) ----------------
__global__ __launch_bounds__(256) void ln_k(
    const float* __restrict__ in, const float* __restrict__ g,
    const float* __restrict__ bt, float* __restrict__ out, __half* __restrict__ outh)
{
    int row = blockIdx.x, tid = threadIdx.x;
    float4 v = ((const float4*)(in + (size_t)row * Dc))[tid];
    __shared__ float red[256];

    red[tid] = v.x + v.y + v.z + v.w; __syncthreads();
    for (int o = 128; o; o >>= 1) { if (tid < o) red[tid] += red[tid + o]; __syncthreads(); }
    float mu = red[0] * (1.0f / Dc);
    __syncthreads();

    float dx = v.x - mu, dy = v.y - mu, dz = v.z - mu, dw = v.w - mu;
    red[tid] = dx * dx + dy * dy + dz * dz + dw * dw; __syncthreads();
    for (int o = 128; o; o >>= 1) { if (tid < o) red[tid] += red[tid + o]; __syncthreads(); }
    float inv = rsqrtf(red[0] * (1.0f / Dc) + 1e-5f);

    float4 gg = ((const float4*)g)[tid];
    float4 bb = ((const float4*)bt)[tid];
    float4 r;
    r.x = dx * inv * gg.x + bb.x;
    r.y = dy * inv * gg.y + bb.y;
    r.z = dz * inv * gg.z + bb.z;
    r.w = dw * inv * gg.w + bb.w;
    ((float4*)(out + (size_t)row * Dc))[tid] = r;
    if (outh) {
        ((__half2*)(outh + (size_t)row * Dc))[2 * tid]     = __floats2half2_rn(r.x, r.y);
        ((__half2*)(outh + (size_t)row * Dc))[2 * tid + 1] = __floats2half2_rn(r.z, r.w);
    }
}

// ---------------- host orchestration ----------------
extern "C" void kernel_launch(void* const* d_in, const int* in_sizes, int n_in,
                              void* d_out, int out_size)
{
    const float* src = (const float*)d_in[0];
    const float* Wq  = (const float*)d_in[1];
    const float* bq  = (const float*)d_in[2];
    const float* Wk  = (const float*)d_in[3];
    const float* bk  = (const float*)d_in[4];
    const float* Wv  = (const float*)d_in[5];
    const float* bv  = (const float*)d_in[6];
    const float* Wo  = (const float*)d_in[7];
    const float* bo  = (const float*)d_in[8];
    const float* W1  = (const float*)d_in[9];
    const float* b1  = (const float*)d_in[10];
    const float* W2  = (const float*)d_in[11];
    const float* b2  = (const float*)d_in[12];
    const float* g1  = (const float*)d_in[13];
    const float* be1 = (const float*)d_in[14];
    const float* g2  = (const float*)d_in[15];
    const float* be2 = (const float*)d_in[16];
    const float* gf  = (const float*)d_in[17];
    const float* bf  = (const float*)d_in[18];

    float *x, *tmp, *qb, *kb, *pe;
    __half *xh, *qh, *kh, *vh, *oh, *ffh, *wqh, *wkh, *wvh, *woh, *w1h, *w2h;
    cudaGetSymbolAddress((void**)&x,   g_x);
    cudaGetSymbolAddress((void**)&tmp, g_tmp);
    cudaGetSymbolAddress((void**)&qb,  g_q);
    cudaGetSymbolAddress((void**)&kb,  g_k);
    cudaGetSymbolAddress((void**)&pe,  g_pe);
    cudaGetSymbolAddress((void**)&xh,  g_xh);
    cudaGetSymbolAddress((void**)&qh,  g_qh);
    cudaGetSymbolAddress((void**)&kh,  g_kh);
    cudaGetSymbolAddress((void**)&vh,  g_vh);
    cudaGetSymbolAddress((void**)&oh,  g_oh);
    cudaGetSymbolAddress((void**)&ffh, g_ffh);
    cudaGetSymbolAddress((void**)&wqh, g_wq);
    cudaGetSymbolAddress((void**)&wkh, g_wk);
    cudaGetSymbolAddress((void**)&wvh, g_wv);
    cudaGetSymbolAddress((void**)&woh, g_wo);
    cudaGetSymbolAddress((void**)&w1h, g_w1);
    cudaGetSymbolAddress((void**)&w2h, g_w2);

    cudaFuncSetAttribute(gemm_w<0>, cudaFuncAttributeMaxDynamicSharedMemorySize, GEMM_DSM);
    cudaFuncSetAttribute(gemm_w<1>, cudaFuncAttributeMaxDynamicSharedMemorySize, GEMM_DSM);
    cudaFuncSetAttribute(gemm_w<2>, cudaFuncAttributeMaxDynamicSharedMemorySize, GEMM_DSM);
    cudaFuncSetAttribute(gemm_w<3>, cudaFuncAttributeMaxDynamicSharedMemorySize, GEMM_DSM);
    cudaFuncSetAttribute(fa_k,      cudaFuncAttributeMaxDynamicSharedMemorySize, FA_DSM);

    // weight convert + transpose (fp32 [K,N] -> fp16 [N,K]), all layers at once
    dim3 wblk(32, 8);
    wconv_t<<<dim3(Dc / 32, Dc / 32, NLc), wblk>>>(Wq, wqh, Dc, Dc);
    wconv_t<<<dim3(Dc / 32, Dc / 32, NLc), wblk>>>(Wk, wkh, Dc, Dc);
    wconv_t<<<dim3(Dc / 32, Dc / 32, NLc), wblk>>>(Wv, wvh, Dc, Dc);
    wconv_t<<<dim3(Dc / 32, Dc / 32, NLc), wblk>>>(Wo, woh, Dc, Dc);
    wconv_t<<<dim3(FFc / 32, Dc / 32, NLc), wblk>>>(W1, w1h, Dc, FFc);
    wconv_t<<<dim3(Dc / 32, FFc / 32, NLc), wblk>>>(W2, w2h, FFc, Dc);

    cudaMemcpyAsync(x, src, sizeof(float) * Mtot * Dc, cudaMemcpyDeviceToDevice);
    f2h_k<<<(Mtot * Dc / 4 + 255) / 256, 256>>>(src, xh, Mtot * Dc / 4);
    pe_k<<<128, 256>>>(pe);

    const int M = Mtot;
    dim3 gD(Dc / 128, M / 128);            // (8, 16)
    dim3 gF(FFc / 128, M / 128);           // (32, 16)
    dim3 gFA(Lc / 128, Bc * Hc);           // (8, 32)

    for (int l = 0; l < NLc; l++) {
        const __half* wq = wqh + (size_t)l * Dc * Dc;
        const __half* wk = wkh + (size_t)l * Dc * Dc;
        const __half* wv = wvh + (size_t)l * Dc * Dc;
        const __half* wo = woh + (size_t)l * Dc * Dc;
        const __half* w1 = w1h + (size_t)l * Dc * FFc;
        const __half* w2 = w2h + (size_t)l * FFc * Dc;

        gemm_w<0><<<gD, 256, GEMM_DSM>>>(xh, wq, bq + l * Dc, nullptr, qb, nullptr, M, Dc, Dc);
        gemm_w<0><<<gD, 256, GEMM_DSM>>>(xh, wk, bk + l * Dc, nullptr, kb, nullptr, M, Dc, Dc);
        gemm_w<1><<<gD, 256, GEMM_DSM>>>(xh, wv, bv + l * Dc, nullptr, nullptr, vh, M, Dc, Dc);

        rope_h<<<(Mtot * Hc) / 8, 256>>>(qb, pe, qh, 0.125f);
        rope_h<<<(Mtot * Hc) / 8, 256>>>(kb, pe, kh, 1.0f);

        fa_k<<<gFA, 256, FA_DSM>>>(qh, kh, vh, oh);

        gemm_w<3><<<gD, 256, GEMM_DSM>>>(oh, wo, bo + l * Dc, x, tmp, nullptr, M, Dc, Dc);
        ln_k<<<M, 256>>>(tmp, g1 + l * Dc, be1 + l * Dc, x, xh);

        gemm_w<2><<<gF, 256, GEMM_DSM>>>(xh, w1, b1 + (size_t)l * FFc, nullptr, nullptr, ffh, M, FFc, Dc);
        gemm_w<3><<<gD, 256, GEMM_DSM>>>(ffh, w2, b2 + l * Dc, x, tmp, nullptr, M, Dc, FFc);
        ln_k<<<M, 256>>>(tmp, g2 + l * Dc, be2 + l * Dc, x, xh);
    }

    ln_k<<<M, 256>>>(x, gf, bf, (float*)d_out, nullptr);
}

// round 6
// speedup vs baseline: 6.2816x; 2.0646x over previous
#include <cuda_runtime.h>
#include <cuda_fp16.h>
#include <mma.h>
#include <math.h>
#include <stdint.h>

using namespace nvcuda;

#define Bc 2
#define Lc 1024
#define Dc 1024
#define Hc 16
#define HDc 64
#define FFc 4096
#define NLc 8
#define Mtot (Bc*Lc)

// ---------------- scratch (device globals; no allocation) ----------------
__device__ float g_x   [Mtot*Dc];
__device__ float g_tmp [Mtot*Dc];
__device__ float g_qkv [(size_t)Mtot*3*Dc];   // fused qkv f32, 24 MB
__device__ float g_pe  [Lc*HDc];
__device__ float g_bqkv[NLc*3*Dc];

__device__ __half g_xh [Mtot*Dc];
__device__ __half g_qh [Mtot*Dc];
__device__ __half g_kh [Mtot*Dc];
__device__ __half g_vh [Mtot*Dc];
__device__ __half g_oh [Mtot*Dc];
__device__ __half g_ffh[(size_t)Mtot*FFc];
__device__ __half g_wqkv[(size_t)NLc*3*Dc*Dc];
__device__ __half g_wo [(size_t)NLc*Dc*Dc];
__device__ __half g_w1 [(size_t)NLc*Dc*FFc];
__device__ __half g_w2 [(size_t)NLc*FFc*Dc];

__device__ __forceinline__ float gelu_exact(float x) {
    return 0.5f * x * (1.0f + erff(x * 0.70710678118654752f));
}
__device__ __forceinline__ void cp_async16(uint32_t saddr, const void* gaddr) {
    asm volatile("cp.async.cg.shared.global [%0], [%1], 16;" :: "r"(saddr), "l"(gaddr));
}
__device__ __forceinline__ uint32_t smem_u32(const void* p) {
    uint32_t a;
    asm("{ .reg .u64 t; cvta.to.shared.u64 t, %1; cvt.u32.u64 %0, t; }" : "=r"(a) : "l"(p));
    return a;
}

// ================= wmma fp16 GEMM with fused epilogue =================
// C[M,N] = A[M,K] @ Bt[N,K]^T ; E0: f32 +bias ; E1: f16 +bias ; E2: f16 gelu(+bias) ; E3: f32 +bias+res
#define BKc 64
#define LDS 72
#define GEMM_DSM (4*128*LDS*2)   // 73728 B A/B double buffers; C tile (67584) aliases
template<int E>
__global__ __launch_bounds__(256) void gemm_w(
    const __half* __restrict__ A, const __half* __restrict__ Bt,
    const float* __restrict__ bias, const float* __restrict__ res,
    float* __restrict__ Cf, __half* __restrict__ Ch, int M, int N, int K)
{
    extern __shared__ char dsm[];
    __half (*As)[128][LDS] = (__half (*)[128][LDS])dsm;
    __half (*Bs)[128][LDS] = (__half (*)[128][LDS])(dsm + 2 * 128 * LDS * 2);
    float* Cs = (float*)dsm;   // aliased; used after mainloop

    const int tid = threadIdx.x;
    const int w = tid >> 5;
    const int wm = w & 1;
    const int wn = w >> 1;
    const int row0 = blockIdx.y * 128, col0 = blockIdx.x * 128;

    wmma::fragment<wmma::accumulator, 16, 16, 16, float> acc[4][2];
#pragma unroll
    for (int i = 0; i < 4; i++)
#pragma unroll
        for (int j = 0; j < 2; j++) wmma::fill_fragment(acc[i][j], 0.0f);

    const int nch = K / BKc;
    auto issue_chunk = [&](int buf, int c0) {
#pragma unroll
        for (int i = 0; i < 4; i++) {
            int s = tid + i * 256;
            int r = s >> 3, cc = (s & 7) * 8;
            cp_async16(smem_u32(&As[buf][r][cc]), A  + (size_t)(row0 + r) * K + c0 + cc);
            cp_async16(smem_u32(&Bs[buf][r][cc]), Bt + (size_t)(col0 + r) * K + c0 + cc);
        }
        asm volatile("cp.async.commit_group;" ::: "memory");
    };

    issue_chunk(0, 0);
    for (int c = 0; c < nch; c++) {
        const int buf = c & 1;
        if (c + 1 < nch) {
            issue_chunk((c + 1) & 1, (c + 1) * BKc);
            asm volatile("cp.async.wait_group 1;" ::: "memory");
        } else {
            asm volatile("cp.async.wait_group 0;" ::: "memory");
        }
        __syncthreads();
#pragma unroll
        for (int kk = 0; kk < 4; kk++) {
            wmma::fragment<wmma::matrix_a, 16, 16, 16, __half, wmma::row_major> af[4];
            wmma::fragment<wmma::matrix_b, 16, 16, 16, __half, wmma::col_major> bf[2];
#pragma unroll
            for (int i = 0; i < 4; i++)
                wmma::load_matrix_sync(af[i], &As[buf][wm * 64 + i * 16][kk * 16], LDS);
#pragma unroll
            for (int j = 0; j < 2; j++)
                wmma::load_matrix_sync(bf[j], &Bs[buf][wn * 32 + j * 16][kk * 16], LDS);
#pragma unroll
            for (int i = 0; i < 4; i++)
#pragma unroll
                for (int j = 0; j < 2; j++)
                    wmma::mma_sync(acc[i][j], af[i], bf[j], acc[i][j]);
        }
        __syncthreads();
    }

    // stage C tile through smem (aliased; all MMA done)
#pragma unroll
    for (int i = 0; i < 4; i++)
#pragma unroll
        for (int j = 0; j < 2; j++)
            wmma::store_matrix_sync(Cs + (size_t)(wm * 64 + i * 16) * 132 + wn * 32 + j * 16,
                                    acc[i][j], 132, wmma::mem_row_major);
    __syncthreads();

#pragma unroll
    for (int it = 0; it < 16; it++) {
        int vlin = tid + it * 256;
        int row = vlin >> 5;
        int vc = (vlin & 31) * 4;
        float4 v = *(float4*)(Cs + (size_t)row * 132 + vc);
        float4 b = *(const float4*)(bias + col0 + vc);
        v.x += b.x; v.y += b.y; v.z += b.z; v.w += b.w;
        size_t gidx = (size_t)(row0 + row) * N + col0 + vc;
        if (E == 2) {
            v.x = gelu_exact(v.x); v.y = gelu_exact(v.y);
            v.z = gelu_exact(v.z); v.w = gelu_exact(v.w);
        }
        if (E == 1 || E == 2) {
            *(__half2*)(Ch + gidx)     = __floats2half2_rn(v.x, v.y);
            *(__half2*)(Ch + gidx + 2) = __floats2half2_rn(v.z, v.w);
        } else {
            if (E == 3) {
                float4 rr = *(const float4*)(res + gidx);
                v.x += rr.x; v.y += rr.y; v.z += rr.z; v.w += rr.w;
            }
            *(float4*)(Cf + gidx) = v;
        }
    }
}

// ================= flash attention v2: warp-private, register O =================
// grid (L/128, B*H); 256 threads. q pre-scaled 1/8. 2 block syncs per KV tile.
#define FA_Q   0                         // 128 x 72 f16 = 18432
#define FA_K   18432                     // 2 x 64 x 72 f16 = 18432
#define FA_V   36864                     // 2 x 64 x 72 f16 = 18432
#define FA_S   55296                     // 8 strips x 16 x 72 f32 = 36864
#define FA_P   92160                     // 8 strips x 16 x 64 f16 = 16384
#define FA_DSM 108544
__global__ __launch_bounds__(256) void fa_k(
    const __half* __restrict__ q, const __half* __restrict__ k,
    const __half* __restrict__ v, __half* __restrict__ o)
{
    extern __shared__ char dsm[];
    __half* Qs = (__half*)(dsm + FA_Q);
    __half* Kb = (__half*)(dsm + FA_K);
    __half* Vb = (__half*)(dsm + FA_V);

    const int tid = threadIdx.x;
    const int w = tid >> 5, lane = tid & 31;
    const int bh = blockIdx.y;
    const int b = bh >> 4, h = bh & 15;
    const int i0 = blockIdx.x * 128;
    const float slope = exp2f(-0.5f * (float)h);

    float* Ssw = (float*)(dsm + FA_S) + w * 16 * 72;
    __half* Psw = (__half*)(dsm + FA_P) + w * 16 * 64;

    // load Q tile (128 x 64 -> ld 72)
#pragma unroll
    for (int i = 0; i < 4; i++) {
        int s = tid + i * 256;
        int r = s >> 3, u = (s & 7) * 8;
        *(uint4*)(Qs + r * 72 + u) = *(const uint4*)(q + (size_t)(b * Lc + i0 + r) * Dc + h * 64 + u);
    }

    auto issue_kv = [&](int buf, int j0) {
        __half* kd = Kb + buf * 64 * 72;
        __half* vd = Vb + buf * 64 * 72;
#pragma unroll
        for (int i = 0; i < 2; i++) {
            int s = tid + i * 256;
            int r = s >> 3, u = (s & 7) * 8;
            cp_async16(smem_u32(kd + r * 72 + u), k + (size_t)(b * Lc + j0 + r) * Dc + h * 64 + u);
            cp_async16(smem_u32(vd + r * 72 + u), v + (size_t)(b * Lc + j0 + r) * Dc + h * 64 + u);
        }
        asm volatile("cp.async.commit_group;" ::: "memory");
    };

    const int rr = lane >> 1;
    const int c0 = (lane & 1) * 32;
    const int i_abs = i0 + w * 16 + rr;

    float Oreg[32];
#pragma unroll
    for (int c = 0; c < 32; c++) Oreg[c] = 0.0f;
    float m_st = -1e30f, l_st = 0.0f;

    issue_kv(0, 0);
    __syncthreads();   // Q visible too

    for (int jt = 0; jt < Lc / 64; jt++) {
        const int buf = jt & 1;
        const int j0 = jt * 64;
        if (jt + 1 < Lc / 64) {
            issue_kv(buf ^ 1, j0 + 64);
            asm volatile("cp.async.wait_group 1;" ::: "memory");
        } else {
            asm volatile("cp.async.wait_group 0;" ::: "memory");
        }
        __syncthreads();   // KV(buf) visible to all

        const __half* kd = Kb + buf * 64 * 72;
        const __half* vd = Vb + buf * 64 * 72;

        // S = Q(16x64) @ K^T(64x64) -> Ssw
        {
            wmma::fragment<wmma::matrix_a, 16, 16, 16, __half, wmma::row_major> af[4];
#pragma unroll
            for (int kk = 0; kk < 4; kk++)
                wmma::load_matrix_sync(af[kk], Qs + (w * 16) * 72 + kk * 16, 72);
#pragma unroll
            for (int n = 0; n < 4; n++) {
                wmma::fragment<wmma::accumulator, 16, 16, 16, float> cfr;
                wmma::fill_fragment(cfr, 0.0f);
#pragma unroll
                for (int kk = 0; kk < 4; kk++) {
                    wmma::fragment<wmma::matrix_b, 16, 16, 16, __half, wmma::col_major> bf;
                    wmma::load_matrix_sync(bf, kd + (n * 16) * 72 + kk * 16, 72);
                    wmma::mma_sync(cfr, af[kk], bf, cfr);
                }
                wmma::store_matrix_sync(Ssw + n * 16, cfr, 72, wmma::mem_row_major);
            }
        }
        __syncwarp();

        // online softmax: lane pair per row (rr), 32 cols each
        {
            float s[32];
            float mx = -1e30f;
#pragma unroll
            for (int c = 0; c < 32; c++) {
                int j_abs = j0 + c0 + c;
                float bias = (i_abs > j_abs) ? slope * (float)(i_abs - j_abs) : 0.0f;
                s[c] = Ssw[rr * 72 + c0 + c] + bias;
                mx = fmaxf(mx, s[c]);
            }
            mx = fmaxf(mx, __shfl_xor_sync(0xffffffffu, mx, 1));
            float m_new = fmaxf(m_st, mx);
            float factor = __expf(m_st - m_new);
            float sum = 0.0f;
#pragma unroll
            for (int c = 0; c < 32; c += 2) {
                float p0 = __expf(s[c] - m_new);
                float p1 = __expf(s[c + 1] - m_new);
                sum += p0 + p1;
                *(__half2*)(Psw + rr * 64 + c0 + c) = __floats2half2_rn(p0, p1);
            }
            sum += __shfl_xor_sync(0xffffffffu, sum, 1);
            m_st = m_new;
            l_st = l_st * factor + sum;
#pragma unroll
            for (int c = 0; c < 32; c++) Oreg[c] *= factor;
        }
        __syncwarp();

        // Onew = P(16x64) @ V(64x64) -> Ssw, then accumulate to registers
        {
            wmma::fragment<wmma::matrix_a, 16, 16, 16, __half, wmma::row_major> af[4];
#pragma unroll
            for (int kk = 0; kk < 4; kk++)
                wmma::load_matrix_sync(af[kk], Psw + kk * 16, 64);
#pragma unroll
            for (int n = 0; n < 4; n++) {
                wmma::fragment<wmma::accumulator, 16, 16, 16, float> cfr;
                wmma::fill_fragment(cfr, 0.0f);
#pragma unroll
                for (int kk = 0; kk < 4; kk++) {
                    wmma::fragment<wmma::matrix_b, 16, 16, 16, __half, wmma::row_major> bf;
                    wmma::load_matrix_sync(bf, vd + (kk * 16) * 72 + n * 16, 72);
                    wmma::mma_sync(cfr, af[kk], bf, cfr);
                }
                wmma::store_matrix_sync(Ssw + n * 16, cfr, 72, wmma::mem_row_major);
            }
        }
        __syncwarp();
#pragma unroll
        for (int c = 0; c < 32; c++) Oreg[c] += Ssw[rr * 72 + c0 + c];
        __syncwarp();

        __syncthreads();   // all warps done with KV(buf) before overwrite
    }

    // final: o = O / l (fp16)
    {
        float inv = 1.0f / l_st;
        size_t gb = (size_t)(b * Lc + i_abs) * Dc + h * 64 + c0;
#pragma unroll
        for (int c = 0; c < 32; c += 2)
            *(__half2*)(o + gb + c) = __floats2half2_rn(Oreg[c] * inv, Oreg[c + 1] * inv);
    }
}

// ================= weight transpose + convert: in[K,N] f32 -> out[N,K] f16 =================
__global__ void wconv_t(const float* __restrict__ in, __half* __restrict__ out,
                        int K, int N, size_t in_ls, size_t out_ls) {
    __shared__ float t[32][33];
    size_t iin = (size_t)blockIdx.z * in_ls;
    size_t ion = (size_t)blockIdx.z * out_ls;
    int n0 = blockIdx.x * 32, k0 = blockIdx.y * 32;
    int tx = threadIdx.x, ty = threadIdx.y;
#pragma unroll
    for (int i = 0; i < 32; i += 8)
        t[ty + i][tx] = in[iin + (size_t)(k0 + ty + i) * N + n0 + tx];
    __syncthreads();
#pragma unroll
    for (int i = 0; i < 32; i += 8)
        out[ion + (size_t)(n0 + ty + i) * K + k0 + tx] = __float2half_rn(t[tx][ty + i]);
}

// ================= misc small kernels =================
__global__ void f2h_k(const float* __restrict__ in, __half* __restrict__ out, int n4) {
    int i = blockIdx.x * blockDim.x + threadIdx.x;
    if (i >= n4) return;
    float4 v = ((const float4*)in)[i];
    ((__half2*)out)[2 * i]     = __floats2half2_rn(v.x, v.y);
    ((__half2*)out)[2 * i + 1] = __floats2half2_rn(v.z, v.w);
}

__global__ void bcat_k(const float* __restrict__ bq, const float* __restrict__ bk,
                       const float* __restrict__ bv, float* __restrict__ out) {
    int i = blockIdx.x * 256 + threadIdx.x;     // NL*3072
    int l = i / (3 * Dc), c = i % (3 * Dc);
    float v = (c < Dc) ? bq[l * Dc + c] : (c < 2 * Dc) ? bk[l * Dc + c - Dc] : bv[l * Dc + c - 2 * Dc];
    out[i] = v;
}

__global__ void pe_k(float* __restrict__ pe) {
    int idx = blockIdx.x * blockDim.x + threadIdx.x;
    if (idx >= Lc * 32) return;
    int pos = idx >> 5, f = idx & 31;
    float inv = powf(10000.0f, -(float)f * (1.0f / 32.0f));
    float ang = (float)pos * inv;
    pe[pos * 64 + f]      = cosf(ang);
    pe[pos * 64 + 32 + f] = sinf(ang);
}

// ---------------- rope on fused qkv (f32) -> qh (scaled), kh, vh (f16) ----------------
__global__ __launch_bounds__(256) void rope_qkv(
    const float* __restrict__ qkv, const float* __restrict__ pe,
    __half* __restrict__ qh, __half* __restrict__ kh, __half* __restrict__ vh)
{
    int w    = blockIdx.x * 8 + (threadIdx.x >> 5);
    int lane = threadIdx.x & 31;
    int h = w & 15;
    int l = (w >> 4) & 1023;
    int b = w >> 14;
    size_t rowq = (size_t)(b * Lc + l);
    const float* base = qkv + rowq * (3 * Dc) + h * 64;
    float c = pe[l * 64 + 2 * lane];
    float s = pe[l * 64 + 2 * lane + 1];

    float qe = base[2 * lane], qo = base[2 * lane + 1];
    __half* pq = qh + rowq * Dc + h * 64;
    pq[lane]      = __float2half_rn((qe * c - qo * s) * 0.125f);
    pq[lane + 32] = __float2half_rn((qe * s + qo * c) * 0.125f);

    float ke = base[Dc + 2 * lane], ko = base[Dc + 2 * lane + 1];
    __half* pk = kh + rowq * Dc + h * 64;
    pk[lane]      = __float2half_rn(ke * c - ko * s);
    pk[lane + 32] = __float2half_rn(ke * s + ko * c);

    __half* pv = vh + rowq * Dc + h * 64;
    pv[lane]      = __float2half_rn(base[2 * Dc + lane]);
    pv[lane + 32] = __float2half_rn(base[2 * Dc + lane + 32]);
}

// ---------------- LayerNorm (writes fp32 + optional fp16 copy) ----------------
__global__ __launch_bounds__(256) void ln_k(
    const float* __restrict__ in, const float* __restrict__ g,
    const float* __restrict__ bt, float* __restrict__ out, __half* __restrict__ outh)
{
    int row = blockIdx.x, tid = threadIdx.x;
    float4 v = ((const float4*)(in + (size_t)row * Dc))[tid];
    __shared__ float red[256];

    red[tid] = v.x + v.y + v.z + v.w; __syncthreads();
    for (int o = 128; o; o >>= 1) { if (tid < o) red[tid] += red[tid + o]; __syncthreads(); }
    float mu = red[0] * (1.0f / Dc);
    __syncthreads();

    float dx = v.x - mu, dy = v.y - mu, dz = v.z - mu, dw = v.w - mu;
    red[tid] = dx * dx + dy * dy + dz * dz + dw * dw; __syncthreads();
    for (int o = 128; o; o >>= 1) { if (tid < o) red[tid] += red[tid + o]; __syncthreads(); }
    float inv = rsqrtf(red[0] * (1.0f / Dc) + 1e-5f);

    float4 gg = ((const float4*)g)[tid];
    float4 bb = ((const float4*)bt)[tid];
    float4 r;
    r.x = dx * inv * gg.x + bb.x;
    r.y = dy * inv * gg.y + bb.y;
    r.z = dz * inv * gg.z + bb.z;
    r.w = dw * inv * gg.w + bb.w;
    ((float4*)(out + (size_t)row * Dc))[tid] = r;
    if (outh) {
        ((__half2*)(outh + (size_t)row * Dc))[2 * tid]     = __floats2half2_rn(r.x, r.y);
        ((__half2*)(outh + (size_t)row * Dc))[2 * tid + 1] = __floats2half2_rn(r.z, r.w);
    }
}

// ---------------- host orchestration ----------------
extern "C" void kernel_launch(void* const* d_in, const int* in_sizes, int n_in,
                              void* d_out, int out_size)
{
    const float* src = (const float*)d_in[0];
    const float* Wq  = (const float*)d_in[1];
    const float* bq  = (const float*)d_in[2];
    const float* Wk  = (const float*)d_in[3];
    const float* bk  = (const float*)d_in[4];
    const float* Wv  = (const float*)d_in[5];
    const float* bv  = (const float*)d_in[6];
    const float* Wo  = (const float*)d_in[7];
    const float* bo  = (const float*)d_in[8];
    const float* W1  = (const float*)d_in[9];
    const float* b1  = (const float*)d_in[10];
    const float* W2  = (const float*)d_in[11];
    const float* b2  = (const float*)d_in[12];
    const float* g1  = (const float*)d_in[13];
    const float* be1 = (const float*)d_in[14];
    const float* g2  = (const float*)d_in[15];
    const float* be2 = (const float*)d_in[16];
    const float* gf  = (const float*)d_in[17];
    const float* bf  = (const float*)d_in[18];

    float *x, *tmp, *qkv, *pe, *bqkv;
    __half *xh, *qh, *kh, *vh, *oh, *ffh, *wqkvh, *woh, *w1h, *w2h;
    cudaGetSymbolAddress((void**)&x,    g_x);
    cudaGetSymbolAddress((void**)&tmp,  g_tmp);
    cudaGetSymbolAddress((void**)&qkv,  g_qkv);
    cudaGetSymbolAddress((void**)&pe,   g_pe);
    cudaGetSymbolAddress((void**)&bqkv, g_bqkv);
    cudaGetSymbolAddress((void**)&xh,   g_xh);
    cudaGetSymbolAddress((void**)&qh,   g_qh);
    cudaGetSymbolAddress((void**)&kh,   g_kh);
    cudaGetSymbolAddress((void**)&vh,   g_vh);
    cudaGetSymbolAddress((void**)&oh,   g_oh);
    cudaGetSymbolAddress((void**)&ffh,  g_ffh);
    cudaGetSymbolAddress((void**)&wqkvh,g_wqkv);
    cudaGetSymbolAddress((void**)&woh,  g_wo);
    cudaGetSymbolAddress((void**)&w1h,  g_w1);
    cudaGetSymbolAddress((void**)&w2h,  g_w2);

    cudaFuncSetAttribute(gemm_w<0>, cudaFuncAttributeMaxDynamicSharedMemorySize, GEMM_DSM);
    cudaFuncSetAttribute(gemm_w<1>, cudaFuncAttributeMaxDynamicSharedMemorySize, GEMM_DSM);
    cudaFuncSetAttribute(gemm_w<2>, cudaFuncAttributeMaxDynamicSharedMemorySize, GEMM_DSM);
    cudaFuncSetAttribute(gemm_w<3>, cudaFuncAttributeMaxDynamicSharedMemorySize, GEMM_DSM);
    cudaFuncSetAttribute(fa_k,      cudaFuncAttributeMaxDynamicSharedMemorySize, FA_DSM);

    // weight convert/transpose. Wq/Wk/Wv go into fused wqkv [l][3072][1024]
    dim3 wblk(32, 8);
    const size_t DD = (size_t)Dc * Dc;
    wconv_t<<<dim3(Dc / 32, Dc / 32, NLc), wblk>>>(Wq, wqkvh,            Dc, Dc, DD, 3 * DD);
    wconv_t<<<dim3(Dc / 32, Dc / 32, NLc), wblk>>>(Wk, wqkvh + DD,       Dc, Dc, DD, 3 * DD);
    wconv_t<<<dim3(Dc / 32, Dc / 32, NLc), wblk>>>(Wv, wqkvh + 2 * DD,   Dc, Dc, DD, 3 * DD);
    wconv_t<<<dim3(Dc / 32, Dc / 32, NLc), wblk>>>(Wo, woh, Dc, Dc, DD, DD);
    wconv_t<<<dim3(FFc / 32, Dc / 32, NLc), wblk>>>(W1, w1h, Dc, FFc, (size_t)Dc * FFc, (size_t)Dc * FFc);
    wconv_t<<<dim3(Dc / 32, FFc / 32, NLc), wblk>>>(W2, w2h, FFc, Dc, (size_t)Dc * FFc, (size_t)Dc * FFc);
    bcat_k<<<NLc * 3 * Dc / 256, 256>>>(bq, bk, bv, bqkv);

    cudaMemcpyAsync(x, src, sizeof(float) * Mtot * Dc, cudaMemcpyDeviceToDevice);
    f2h_k<<<(Mtot * Dc / 4 + 255) / 256, 256>>>(src, xh, Mtot * Dc / 4);
    pe_k<<<128, 256>>>(pe);

    const int M = Mtot;
    dim3 gQKV(3 * Dc / 128, M / 128);      // (24, 16)
    dim3 gD(Dc / 128, M / 128);            // (8, 16)
    dim3 gF(FFc / 128, M / 128);           // (32, 16)
    dim3 gFA(Lc / 128, Bc * Hc);           // (8, 32)

    for (int l = 0; l < NLc; l++) {
        const __half* wqkvl = wqkvh + (size_t)l * 3 * DD;
        const __half* wo = woh + (size_t)l * DD;
        const __half* w1 = w1h + (size_t)l * Dc * FFc;
        const __half* w2 = w2h + (size_t)l * FFc * Dc;

        gemm_w<0><<<gQKV, 256, GEMM_DSM>>>(xh, wqkvl, bqkv + l * 3 * Dc, nullptr, qkv, nullptr, M, 3 * Dc, Dc);
        rope_qkv<<<(Mtot * Hc) / 8, 256>>>(qkv, pe, qh, kh, vh);
        fa_k<<<gFA, 256, FA_DSM>>>(qh, kh, vh, oh);

        gemm_w<3><<<gD, 256, GEMM_DSM>>>(oh, wo, bo + l * Dc, x, tmp, nullptr, M, Dc, Dc);
        ln_k<<<M, 256>>>(tmp, g1 + l * Dc, be1 + l * Dc, x, xh);

        gemm_w<2><<<gF, 256, GEMM_DSM>>>(xh, w1, b1 + (size_t)l * FFc, nullptr, nullptr, ffh, M, FFc, Dc);
        gemm_w<3><<<gD, 256, GEMM_DSM>>>(ffh, w2, b2 + l * Dc, x, tmp, nullptr, M, Dc, FFc);
        ln_k<<<M, 256>>>(tmp, g2 + l * Dc, be2 + l * Dc, x, xh);
    }

    ln_k<<<M, 256>>>(x, gf, bf, (float*)d_out, nullptr);
}